// round 8
// baseline (speedup 1.0000x reference)
#include <cuda_runtime.h>
#include <stdint.h>

// out[r, :] = sum over edges (r, c) of weight[c, :]
// adj: [2, nnz] (rows then cols), dtype int64 OR int32 (runtime-detected)
// weight: [size, 256] float32 ; out: [size, 256] float32
//
// R7: single persistent kernel builds CSR (zero+detect+hist+scan+fill) with
// software grid barriers (148 co-resident blocks), then one wide gather-sum
// kernel. Kills ~20us of per-launch overhead from the 7-kernel pipeline.

#define OUTF 256
#define MAXN   (1 << 17)   // max rows   (problem: 100000)
#define MAXNNZ (1 << 17)   // max edges  (problem: 100000)
#define NB 148             // persistent blocks (<= SM count on B300/GB300)
#define NT 256

__device__ int g_adj_is64;
__device__ int g_count[MAXN];
__device__ int g_rowptr[MAXN + 1];
__device__ int g_cursor[MAXN];
__device__ int g_cols[MAXNNZ];
__device__ int g_chunk_sums[NB];
__device__ int g_chunk_offsets[NB];
__device__ unsigned g_bar_count;   // zero-init, returns to 0 each barrier
__device__ unsigned g_bar_gen;     // monotonic across replays (wrap-safe)

// ---------------------------------------------------------- grid barrier
__device__ __forceinline__ void grid_barrier() {
    __syncthreads();
    if (threadIdx.x == 0) {
        __threadfence();
        unsigned gen = *(volatile unsigned*)&g_bar_gen;  // read BEFORE arrive
        if (atomicAdd(&g_bar_count, 1u) == NB - 1) {
            g_bar_count = 0;
            __threadfence();
            atomicAdd(&g_bar_gen, 1u);                   // release
        } else {
            while (*(volatile unsigned*)&g_bar_gen == gen) { }
        }
        __threadfence();
    }
    __syncthreads();
}

// -------------------------------------------- persistent CSR build kernel
__global__ void __launch_bounds__(NT)
build_csr_kernel(const void* __restrict__ adj, int n, int nnz, int n_check) {
    const int tid = threadIdx.x;
    const int gtid = blockIdx.x * NT + tid;
    const int gstride = NB * NT;
    __shared__ int sh[NT];

    // P0: zero counts; block0/warp0 sniffs dtype (parallel, independent loads)
    for (int i = gtid; i < n; i += gstride) g_count[i] = 0;
    if (blockIdx.x == 0 && tid < 32) {
        // int64 indices are all in [0, n); int32-pairs read as int64 are
        // out of range with overwhelming probability over 64 samples.
        const long long* a = (const long long*)adj;
        int ok = 1;
        for (int k = tid; k < n_check; k += 32) {
            long long v = a[k];
            if (v < 0 || v >= (long long)n) ok = 0;
        }
        unsigned m = __ballot_sync(0xFFFFFFFFu, ok);
        if (tid == 0) g_adj_is64 = (m == 0xFFFFFFFFu) ? 1 : 0;
    }
    grid_barrier();

    const int is64 = g_adj_is64;

    // P1: row histogram
    if (is64) {
        const long long* a = (const long long*)adj;
        for (int e = gtid; e < nnz; e += gstride)
            atomicAdd(&g_count[(int)a[e]], 1);
    } else {
        const int* a = (const int*)adj;
        for (int e = gtid; e < nnz; e += gstride)
            atomicAdd(&g_count[a[e]], 1);
    }
    grid_barrier();

    // P2: per-block chunk totals
    const int chunk = (n + NB - 1) / NB;
    const int lo = blockIdx.x * chunk;
    const int hi = min(lo + chunk, n);
    {
        int s = 0;
        for (int i = lo + tid; i < hi; i += NT) s += g_count[i];
        sh[tid] = s;
        __syncthreads();
        for (int off = NT >> 1; off > 0; off >>= 1) {
            if (tid < off) sh[tid] += sh[tid + off];
            __syncthreads();
        }
        if (tid == 0) g_chunk_sums[blockIdx.x] = sh[0];
    }
    grid_barrier();

    // P3: block 0 exclusive-scans the NB chunk totals
    if (blockIdx.x == 0) {
        int v = (tid < NB) ? g_chunk_sums[tid] : 0;
        sh[tid] = v;
        __syncthreads();
        for (int off = 1; off < NT; off <<= 1) {
            int x = (tid >= off) ? sh[tid - off] : 0;
            __syncthreads();
            sh[tid] += x;
            __syncthreads();
        }
        if (tid < NB) g_chunk_offsets[tid] = sh[tid] - v;
        if (tid == NB - 1) g_rowptr[n] = sh[tid];
    }
    grid_barrier();

    // P4: per-block exclusive scan of its chunk -> rowptr + cursor
    {
        int running = g_chunk_offsets[blockIdx.x];
        for (int base = lo; base < hi; base += NT) {
            int i = base + tid;
            int v = (i < hi) ? g_count[i] : 0;
            sh[tid] = v;
            __syncthreads();
            for (int off = 1; off < NT; off <<= 1) {
                int x = (tid >= off) ? sh[tid - off] : 0;
                __syncthreads();
                sh[tid] += x;
                __syncthreads();
            }
            if (i < hi) {
                int excl = running + sh[tid] - v;
                g_rowptr[i] = excl;
                g_cursor[i] = excl;
            }
            running += sh[NT - 1];
            __syncthreads();
        }
    }
    grid_barrier();

    // P5: bucket fill
    if (is64) {
        const long long* a = (const long long*)adj;
        for (int e = gtid; e < nnz; e += gstride) {
            int r = (int)a[e];
            int c = (int)a[nnz + e];
            g_cols[atomicAdd(&g_cursor[r], 1)] = c;
        }
    } else {
        const int* a = (const int*)adj;
        for (int e = gtid; e < nnz; e += gstride) {
            int r = a[e];
            int c = a[nnz + e];
            g_cols[atomicAdd(&g_cursor[r], 1)] = c;
        }
    }
}

// -------------------------------------------------------- K2: gather-sum
// 64 threads per row (64 x float4 = 256 floats), 4 rows per 256-thr block.
// Streaming stores keep out-writes from evicting hot weight rows in L2.
__global__ void __launch_bounds__(256)
gather_kernel(const float* __restrict__ weight,
              float* __restrict__ out, int n) {
    int row = blockIdx.x * 4 + (threadIdx.x >> 6);
    int t = threadIdx.x & 63;
    if (row >= n) return;
    int beg = g_rowptr[row];
    int end = g_rowptr[row + 1];
    float4 acc = make_float4(0.f, 0.f, 0.f, 0.f);
    for (int e = beg; e < end; e++) {
        int c = g_cols[e];   // broadcast across the 64-thread group
        float4 v = __ldg((const float4*)(weight + (long long)c * OUTF) + t);
        acc.x += v.x; acc.y += v.y; acc.z += v.z; acc.w += v.w;
    }
    __stcs((float4*)(out + (long long)row * OUTF) + t, acc);
}

// --------------------------------------------- fallback (capacity exceed)
__device__ int g_fb_is64;
__global__ void fb_detect_kernel(const long long* __restrict__ adj,
                                 long long nrows, int n_check) {
    if (threadIdx.x < 32) {
        int ok = 1;
        for (int k = threadIdx.x; k < n_check; k += 32) {
            long long v = adj[k];
            if (v < 0 || v >= nrows) ok = 0;
        }
        unsigned m = __ballot_sync(0xFFFFFFFFu, ok);
        if (threadIdx.x == 0) g_fb_is64 = (m == 0xFFFFFFFFu) ? 1 : 0;
    }
}
__global__ void zero_kernel(float4* __restrict__ out, long long n4) {
    long long i = (long long)blockIdx.x * blockDim.x + threadIdx.x;
    long long stride = (long long)gridDim.x * blockDim.x;
    float4 z = make_float4(0.f, 0.f, 0.f, 0.f);
    for (; i < n4; i += stride) out[i] = z;
}
__global__ void __launch_bounds__(256)
scatter_kernel(const void* __restrict__ adj,
               const float* __restrict__ weight,
               float* __restrict__ out, int nnz) {
    int edge = blockIdx.x * 4 + (threadIdx.x >> 6);
    int t = threadIdx.x & 63;
    if (edge >= nnz) return;
    long long r, c;
    if (g_fb_is64) {
        const long long* a = (const long long*)adj;
        r = a[edge]; c = a[nnz + edge];
    } else {
        const int* a = (const int*)adj;
        r = a[edge]; c = a[nnz + edge];
    }
    float4 v = __ldg((const float4*)(weight + c * OUTF) + t);
    float* o = out + r * OUTF + (long long)t * 4;
    atomicAdd(o + 0, v.x);
    atomicAdd(o + 1, v.y);
    atomicAdd(o + 2, v.z);
    atomicAdd(o + 3, v.w);
}

extern "C" void kernel_launch(void* const* d_in, const int* in_sizes, int n_in,
                              void* d_out, int out_size) {
    const void* adj = d_in[0];
    const float* weight = (const float*)d_in[2];
    float* out = (float*)d_out;

    int nnz = in_sizes[0] / 2;
    int n = out_size / OUTF;
    int n_check = nnz < 64 ? nnz : 64;

    if (n <= MAXN && nnz <= MAXNNZ) {
        build_csr_kernel<<<NB, NT>>>(adj, n, nnz, n_check);
        gather_kernel<<<(n + 3) / 4, 256>>>(weight, out, n);
    } else {
        fb_detect_kernel<<<1, 32>>>((const long long*)adj, (long long)n,
                                    n_check);
        long long n4 = (long long)out_size / 4;
        int zblocks = (int)((n4 + 255) / 256);
        if (zblocks < 1) zblocks = 1;
        zero_kernel<<<zblocks, 256>>>((float4*)out, n4);
        int sblocks = (nnz + 3) / 4;
        if (sblocks < 1) sblocks = 1;
        scatter_kernel<<<sblocks, 256>>>(adj, weight, out, nnz);
    }
}

// round 9
// speedup vs baseline: 1.1373x; 1.1373x over previous
#include <cuda_runtime.h>
#include <stdint.h>

// out[r, :] = sum over edges (r, c) of weight[c, :]
// adj: [2, nnz] (rows then cols), dtype int64 OR int32 (runtime-detected)
// weight: [size, 256] float32 ; out: [size, 256] float32
//
// R9: no scan, no CSR. Fixed-capacity row buckets (CAP=8) + exact overflow
// list, built in one persistent kernel with a SINGLE grid barrier. Gather
// processes 4 rows per warp (8 floats/thread/row) for 4-8x memory-level
// parallelism vs the serial per-row chain that left R8 latency-bound.

#define OUTF 256
#define MAXN   (1 << 17)   // max rows   (problem: 100000)
#define MAXNNZ (1 << 17)   // max edges  (problem: 100000)
#define CAP 8              // bucket slots per row (Poisson(1): P(deg>8)~1e-7)
#define NB 148             // persistent blocks (<= SM count)
#define NT 256

__device__ int g_adj_is64;
__device__ int g_bcount[MAXN];          // per-row edge count
__device__ int g_slots[MAXN * CAP];     // 4MB bucket storage (stays in L2)
__device__ int2 g_ovf[MAXNNZ];          // exact overflow (worst case all edges)
__device__ int g_ovf_count;
__device__ unsigned g_bar_count;        // returns to 0 each barrier
__device__ unsigned g_bar_gen;          // monotonic across graph replays

// ---------------------------------------------------------- grid barrier
__device__ __forceinline__ void grid_barrier() {
    __syncthreads();
    if (threadIdx.x == 0) {
        __threadfence();
        unsigned gen = *(volatile unsigned*)&g_bar_gen;  // read BEFORE arrive
        if (atomicAdd(&g_bar_count, 1u) == NB - 1) {
            g_bar_count = 0;
            __threadfence();
            atomicAdd(&g_bar_gen, 1u);                   // release
        } else {
            while (*(volatile unsigned*)&g_bar_gen == gen) { }
        }
        __threadfence();
    }
    __syncthreads();
}

// ---------------------------------------- K1: bucket build (1 barrier)
__global__ void __launch_bounds__(NT)
build_kernel(const void* __restrict__ adj, int n, int nnz, int n_check) {
    const int tid = threadIdx.x;
    const int gtid = blockIdx.x * NT + tid;
    const int gstride = NB * NT;

    // P0: zero counts; block0/warp0 sniffs dtype with parallel loads
    for (int i = gtid; i < n; i += gstride) g_bcount[i] = 0;
    if (blockIdx.x == 0) {
        if (tid == 0) g_ovf_count = 0;
        if (tid < 32) {
            // int64 indices are all in [0, n); int32-pairs read as int64
            // are out of range with overwhelming probability (64 samples).
            const long long* a = (const long long*)adj;
            int ok = 1;
            for (int k = tid; k < n_check; k += 32) {
                long long v = a[k];
                if (v < 0 || v >= (long long)n) ok = 0;
            }
            unsigned m = __ballot_sync(0xFFFFFFFFu, ok);
            if (tid == 0) g_adj_is64 = (m == 0xFFFFFFFFu) ? 1 : 0;
        }
    }
    grid_barrier();

    // P1: bucket fill
    const int is64 = g_adj_is64;
    if (is64) {
        const long long* a = (const long long*)adj;
        for (int e = gtid; e < nnz; e += gstride) {
            int r = (int)a[e];
            int c = (int)a[nnz + e];
            int pos = atomicAdd(&g_bcount[r], 1);
            if (pos < CAP) g_slots[r * CAP + pos] = c;
            else { int o = atomicAdd(&g_ovf_count, 1); g_ovf[o] = make_int2(r, c); }
        }
    } else {
        const int* a = (const int*)adj;
        for (int e = gtid; e < nnz; e += gstride) {
            int r = a[e];
            int c = a[nnz + e];
            int pos = atomicAdd(&g_bcount[r], 1);
            if (pos < CAP) g_slots[r * CAP + pos] = c;
            else { int o = atomicAdd(&g_ovf_count, 1); g_ovf[o] = make_int2(r, c); }
        }
    }
}

// --------------------------------------------------------- K2: gather
// One warp per 4 rows. Each thread owns 8 floats per row (2 float4s at
// lane and lane+32). Up to 8 independent float4 LDGs in flight per warp.
__global__ void __launch_bounds__(256)
gather_kernel(const float* __restrict__ weight, float* __restrict__ out,
              int n) {
    const int warp = (blockIdx.x * 256 + threadIdx.x) >> 5;
    const int lane = threadIdx.x & 31;
    const int row0 = warp * 4;
    if (row0 >= n) return;
    const int nr = min(4, n - row0);

    int cnt[4], lim[4];
    #pragma unroll
    for (int r = 0; r < 4; r++) {
        cnt[r] = (r < nr) ? __ldg(&g_bcount[row0 + r]) : 0;
        lim[r] = min(cnt[r], CAP);
    }
    int kmax = max(max(lim[0], lim[1]), max(lim[2], lim[3]));

    float4 acc[4][2];
    #pragma unroll
    for (int r = 0; r < 4; r++) {
        acc[r][0] = make_float4(0.f, 0.f, 0.f, 0.f);
        acc[r][1] = make_float4(0.f, 0.f, 0.f, 0.f);
    }

    const float4* w = (const float4*)weight;   // 64 float4 per row
    for (int k = 0; k < kmax; k++) {
        int c[4];
        #pragma unroll
        for (int r = 0; r < 4; r++)
            c[r] = (k < lim[r]) ? __ldg(&g_slots[(row0 + r) * CAP + k]) : -1;
        #pragma unroll
        for (int r = 0; r < 4; r++) {
            if (c[r] >= 0) {
                const float4* p = w + (size_t)c[r] * 64;
                float4 v0 = __ldg(p + lane);
                float4 v1 = __ldg(p + lane + 32);
                acc[r][0].x += v0.x; acc[r][0].y += v0.y;
                acc[r][0].z += v0.z; acc[r][0].w += v0.w;
                acc[r][1].x += v1.x; acc[r][1].y += v1.y;
                acc[r][1].z += v1.z; acc[r][1].w += v1.w;
            }
        }
    }

    // Overflow path (rows with degree > CAP) — essentially never taken for
    // random data; exact for adversarial inputs.
    if ((cnt[0] | cnt[1] | cnt[2] | cnt[3]) > CAP) {
        int novf = *(volatile int*)&g_ovf_count;
        for (int e = 0; e < novf; e++) {
            int2 rc = g_ovf[e];
            int d = rc.x - row0;
            if (d >= 0 && d < nr) {
                const float4* p = w + (size_t)rc.y * 64;
                float4 v0 = __ldg(p + lane);
                float4 v1 = __ldg(p + lane + 32);
                acc[d][0].x += v0.x; acc[d][0].y += v0.y;
                acc[d][0].z += v0.z; acc[d][0].w += v0.w;
                acc[d][1].x += v1.x; acc[d][1].y += v1.y;
                acc[d][1].z += v1.z; acc[d][1].w += v1.w;
            }
        }
    }

    #pragma unroll
    for (int r = 0; r < 4; r++) {
        if (r < nr) {
            float4* o = (float4*)out + (size_t)(row0 + r) * 64;
            __stcs(o + lane, acc[r][0]);        // out is never re-read:
            __stcs(o + lane + 32, acc[r][1]);   // evict-first, save L2 for weight
        }
    }
}

// --------------------------------------------- fallback (capacity exceed)
__device__ int g_fb_is64;
__global__ void fb_detect_kernel(const long long* __restrict__ adj,
                                 long long nrows, int n_check) {
    if (threadIdx.x < 32) {
        int ok = 1;
        for (int k = threadIdx.x; k < n_check; k += 32) {
            long long v = adj[k];
            if (v < 0 || v >= nrows) ok = 0;
        }
        unsigned m = __ballot_sync(0xFFFFFFFFu, ok);
        if (threadIdx.x == 0) g_fb_is64 = (m == 0xFFFFFFFFu) ? 1 : 0;
    }
}
__global__ void zero_kernel(float4* __restrict__ out, long long n4) {
    long long i = (long long)blockIdx.x * blockDim.x + threadIdx.x;
    long long stride = (long long)gridDim.x * blockDim.x;
    float4 z = make_float4(0.f, 0.f, 0.f, 0.f);
    for (; i < n4; i += stride) out[i] = z;
}
__global__ void __launch_bounds__(256)
scatter_kernel(const void* __restrict__ adj,
               const float* __restrict__ weight,
               float* __restrict__ out, int nnz) {
    int edge = blockIdx.x * 4 + (threadIdx.x >> 6);
    int t = threadIdx.x & 63;
    if (edge >= nnz) return;
    long long r, c;
    if (g_fb_is64) {
        const long long* a = (const long long*)adj;
        r = a[edge]; c = a[nnz + edge];
    } else {
        const int* a = (const int*)adj;
        r = a[edge]; c = a[nnz + edge];
    }
    float4 v = __ldg((const float4*)(weight + c * OUTF) + t);
    float* o = out + r * OUTF + (long long)t * 4;
    atomicAdd(o + 0, v.x);
    atomicAdd(o + 1, v.y);
    atomicAdd(o + 2, v.z);
    atomicAdd(o + 3, v.w);
}

extern "C" void kernel_launch(void* const* d_in, const int* in_sizes, int n_in,
                              void* d_out, int out_size) {
    const void* adj = d_in[0];
    const float* weight = (const float*)d_in[2];
    float* out = (float*)d_out;

    int nnz = in_sizes[0] / 2;
    int n = out_size / OUTF;
    int n_check = nnz < 64 ? nnz : 64;

    if (n <= MAXN && nnz <= MAXNNZ) {
        build_kernel<<<NB, NT>>>(adj, n, nnz, n_check);
        int warps = (n + 3) / 4;
        int blocks = (warps + 7) / 8;             // 8 warps per block
        gather_kernel<<<blocks, 256>>>(weight, out, n);
    } else {
        fb_detect_kernel<<<1, 32>>>((const long long*)adj, (long long)n,
                                    n_check);
        long long n4 = (long long)out_size / 4;
        int zblocks = (int)((n4 + 255) / 256);
        if (zblocks < 1) zblocks = 1;
        zero_kernel<<<zblocks, 256>>>((float4*)out, n4);
        int sblocks = (nnz + 3) / 4;
        if (sblocks < 1) sblocks = 1;
        scatter_kernel<<<sblocks, 256>>>(adj, weight, out, nnz);
    }
}

// round 10
// speedup vs baseline: 1.4458x; 1.2712x over previous
#include <cuda_runtime.h>
#include <stdint.h>

// out[r, :] = sum over edges (r, c) of weight[c, :]
// adj: [2, nnz] (rows then cols), dtype int64 OR int32 (runtime-detected)
// weight: [size, 256] float32 ; out: [size, 256] float32
//
// R10: bucket build split into 2 light kernels (no grid barrier). Gather is
// warp-per-row: the whole 8-slot bucket is read in ONE 32B wavefront and
// distributed via shfl; weight rows loaded in independent pairs (unroll-2),
// 2 float4 accumulators -> ~48 regs, high occupancy AND high MLP.

#define OUTF 256
#define MAXN   (1 << 17)   // max rows   (problem: 100000)
#define MAXNNZ (1 << 17)   // max edges  (problem: 100000)
#define CAP 8              // bucket slots per row (Poisson(1): P(deg>8)~1e-7)

__device__ int g_adj_is64;
__device__ int g_bcount[MAXN];          // per-row edge count
__device__ int g_slots[MAXN * CAP + 32];// bucket storage (+pad for lane reads)
__device__ int2 g_ovf[MAXNNZ];          // exact overflow list
__device__ int g_ovf_count;

// ------------------------------------------ K1: zero counts + dtype sniff
__global__ void __launch_bounds__(256)
init_kernel(const long long* __restrict__ adj, int n, int n_check) {
    int i = blockIdx.x * blockDim.x + threadIdx.x;
    int stride = gridDim.x * blockDim.x;
    for (; i < n; i += stride) g_bcount[i] = 0;
    if (blockIdx.x == 0) {
        if (threadIdx.x == 0) g_ovf_count = 0;
        if (threadIdx.x < 32) {
            // int64 indices are all in [0, n); int32-pairs read as int64
            // are out of range with overwhelming probability (64 samples).
            int ok = 1;
            for (int k = threadIdx.x; k < n_check; k += 32) {
                long long v = adj[k];
                if (v < 0 || v >= (long long)n) ok = 0;
            }
            unsigned m = __ballot_sync(0xFFFFFFFFu, ok);
            if (threadIdx.x == 0) g_adj_is64 = (m == 0xFFFFFFFFu) ? 1 : 0;
        }
    }
}

// --------------------------------------------------- K2: bucket fill
__global__ void __launch_bounds__(256)
fill_kernel(const void* __restrict__ adj, int nnz) {
    int e = blockIdx.x * blockDim.x + threadIdx.x;
    int stride = gridDim.x * blockDim.x;
    const int is64 = g_adj_is64;
    if (is64) {
        const long long* a = (const long long*)adj;
        for (; e < nnz; e += stride) {
            int r = (int)a[e];
            int c = (int)a[nnz + e];
            int pos = atomicAdd(&g_bcount[r], 1);
            if (pos < CAP) g_slots[r * CAP + pos] = c;
            else { int o = atomicAdd(&g_ovf_count, 1); g_ovf[o] = make_int2(r, c); }
        }
    } else {
        const int* a = (const int*)adj;
        for (; e < nnz; e += stride) {
            int r = a[e];
            int c = a[nnz + e];
            int pos = atomicAdd(&g_bcount[r], 1);
            if (pos < CAP) g_slots[r * CAP + pos] = c;
            else { int o = atomicAdd(&g_ovf_count, 1); g_ovf[o] = make_int2(r, c); }
        }
    }
}

// --------------------------------------------------------- K3: gather
// One warp per row. Lanes 0..7 carry the row's bucket (one 32B wavefront);
// indices distributed by shfl. Each thread owns 8 floats (2 float4s).
__global__ void __launch_bounds__(256)
gather_kernel(const float* __restrict__ weight, float* __restrict__ out,
              int n) {
    const int row  = (blockIdx.x * 256 + threadIdx.x) >> 5;
    const int lane = threadIdx.x & 31;
    if (row >= n) return;

    const int cnt = __ldg(&g_bcount[row]);               // warp-uniform
    const int slot = __ldg(&g_slots[row * CAP + (lane & (CAP - 1))]);
    const int m = min(cnt, CAP);

    const float4* w = (const float4*)weight;             // 64 float4 per row
    float4 a0 = make_float4(0.f, 0.f, 0.f, 0.f);
    float4 a1 = make_float4(0.f, 0.f, 0.f, 0.f);

    int k = 0;
    for (; k + 2 <= m; k += 2) {                         // independent pair
        int ca = __shfl_sync(0xFFFFFFFFu, slot, k);
        int cb = __shfl_sync(0xFFFFFFFFu, slot, k + 1);
        const float4* pa = w + (size_t)ca * 64;
        const float4* pb = w + (size_t)cb * 64;
        float4 va0 = __ldg(pa + lane);
        float4 va1 = __ldg(pa + lane + 32);
        float4 vb0 = __ldg(pb + lane);
        float4 vb1 = __ldg(pb + lane + 32);
        a0.x += va0.x + vb0.x; a0.y += va0.y + vb0.y;
        a0.z += va0.z + vb0.z; a0.w += va0.w + vb0.w;
        a1.x += va1.x + vb1.x; a1.y += va1.y + vb1.y;
        a1.z += va1.z + vb1.z; a1.w += va1.w + vb1.w;
    }
    if (k < m) {
        int ca = __shfl_sync(0xFFFFFFFFu, slot, k);
        const float4* pa = w + (size_t)ca * 64;
        float4 va0 = __ldg(pa + lane);
        float4 va1 = __ldg(pa + lane + 32);
        a0.x += va0.x; a0.y += va0.y; a0.z += va0.z; a0.w += va0.w;
        a1.x += va1.x; a1.y += va1.y; a1.z += va1.z; a1.w += va1.w;
    }

    // Overflow (deg > CAP): exact, essentially never taken for random data.
    if (cnt > CAP) {
        int novf = *(volatile int*)&g_ovf_count;
        for (int e = 0; e < novf; e++) {
            int2 rc = g_ovf[e];
            if (rc.x == row) {
                const float4* p = w + (size_t)rc.y * 64;
                float4 v0 = __ldg(p + lane);
                float4 v1 = __ldg(p + lane + 32);
                a0.x += v0.x; a0.y += v0.y; a0.z += v0.z; a0.w += v0.w;
                a1.x += v1.x; a1.y += v1.y; a1.z += v1.z; a1.w += v1.w;
            }
        }
    }

    float4* o = (float4*)out + (size_t)row * 64;
    o[lane]      = a0;                                   // plain stores (A/B vs __stcs)
    o[lane + 32] = a1;
}

// --------------------------------------------- fallback (capacity exceed)
__device__ int g_fb_is64;
__global__ void fb_detect_kernel(const long long* __restrict__ adj,
                                 long long nrows, int n_check) {
    if (threadIdx.x < 32) {
        int ok = 1;
        for (int k = threadIdx.x; k < n_check; k += 32) {
            long long v = adj[k];
            if (v < 0 || v >= nrows) ok = 0;
        }
        unsigned m = __ballot_sync(0xFFFFFFFFu, ok);
        if (threadIdx.x == 0) g_fb_is64 = (m == 0xFFFFFFFFu) ? 1 : 0;
    }
}
__global__ void zero_kernel(float4* __restrict__ out, long long n4) {
    long long i = (long long)blockIdx.x * blockDim.x + threadIdx.x;
    long long stride = (long long)gridDim.x * blockDim.x;
    float4 z = make_float4(0.f, 0.f, 0.f, 0.f);
    for (; i < n4; i += stride) out[i] = z;
}
__global__ void __launch_bounds__(256)
scatter_kernel(const void* __restrict__ adj,
               const float* __restrict__ weight,
               float* __restrict__ out, int nnz) {
    int edge = blockIdx.x * 4 + (threadIdx.x >> 6);
    int t = threadIdx.x & 63;
    if (edge >= nnz) return;
    long long r, c;
    if (g_fb_is64) {
        const long long* a = (const long long*)adj;
        r = a[edge]; c = a[nnz + edge];
    } else {
        const int* a = (const int*)adj;
        r = a[edge]; c = a[nnz + edge];
    }
    float4 v = __ldg((const float4*)(weight + c * OUTF) + t);
    float* o = out + r * OUTF + (long long)t * 4;
    atomicAdd(o + 0, v.x);
    atomicAdd(o + 1, v.y);
    atomicAdd(o + 2, v.z);
    atomicAdd(o + 3, v.w);
}

extern "C" void kernel_launch(void* const* d_in, const int* in_sizes, int n_in,
                              void* d_out, int out_size) {
    const void* adj = d_in[0];
    const float* weight = (const float*)d_in[2];
    float* out = (float*)d_out;

    int nnz = in_sizes[0] / 2;
    int n = out_size / OUTF;
    int n_check = nnz < 64 ? nnz : 64;

    if (n <= MAXN && nnz <= MAXNNZ) {
        init_kernel<<<160, 256>>>((const long long*)adj, n, n_check);
        fill_kernel<<<(nnz + 255) / 256 < 296 ? (nnz + 255) / 256 : 296,
                      256>>>(adj, nnz);
        int warps = n;                       // 1 warp per row
        int blocks = (warps + 7) / 8;        // 8 warps per 256-thr block
        gather_kernel<<<blocks, 256>>>(weight, out, n);
    } else {
        fb_detect_kernel<<<1, 32>>>((const long long*)adj, (long long)n,
                                    n_check);
        long long n4 = (long long)out_size / 4;
        int zblocks = (int)((n4 + 255) / 256);
        if (zblocks < 1) zblocks = 1;
        zero_kernel<<<zblocks, 256>>>((float4*)out, n4);
        int sblocks = (nnz + 3) / 4;
        if (sblocks < 1) sblocks = 1;
        scatter_kernel<<<sblocks, 256>>>(adj, weight, out, nnz);
    }
}